// round 1
// baseline (speedup 1.0000x reference)
#include <cuda_runtime.h>
#include <math.h>

#define QN 2048
#define DN 256
#define CN 10
#define SN 16
#define RN 160
#define H0 256
#define H1N 128
#define H2N 64

typedef unsigned long long ull;

__device__ float g_qproj[QN * H0];
__device__ float g_iproj[RN * H0];

// ---------------------------------------------------------------------------
// Prep: out[m][n] = sum_k X[m][k] * W[k][n] (+bias). X: [nrows, 256], W rows
// stride 256 (row-major [256,256] slice of W1). 8 rows per block, 256 threads.
// ---------------------------------------------------------------------------
__global__ void proj_kernel(const float* __restrict__ X, int nrows,
                            const float* __restrict__ W,
                            const float* __restrict__ bias,
                            float* __restrict__ out) {
    __shared__ float xs[8][DN];
    int m0 = blockIdx.x * 8;
    int n = threadIdx.x;
#pragma unroll
    for (int mi = 0; mi < 8; mi++) {
        int m = m0 + mi;
        xs[mi][n] = (m < nrows) ? X[m * DN + n] : 0.f;
    }
    __syncthreads();
    float b = bias ? bias[n] : 0.f;
    float acc[8];
#pragma unroll
    for (int mi = 0; mi < 8; mi++) acc[mi] = b;
#pragma unroll 4
    for (int k = 0; k < DN; k++) {
        float w = W[k * H0 + n];
#pragma unroll
        for (int mi = 0; mi < 8; mi++) acc[mi] = fmaf(xs[mi][k], w, acc[mi]);
    }
#pragma unroll
    for (int mi = 0; mi < 8; mi++) {
        int m = m0 + mi;
        if (m < nrows) out[m * H0 + n] = acc[mi];
    }
}

// ---------------------------------------------------------------------------
// Packed fp32x2 helpers (Blackwell: doubles fp32 FMA rate vs 3-reg FFMA)
// ---------------------------------------------------------------------------
__device__ __forceinline__ ull pack2(float x) {
    ull r;
    unsigned u = __float_as_uint(x);
    asm("mov.b64 %0, {%1, %2};" : "=l"(r) : "r"(u), "r"(u));
    return r;
}
__device__ __forceinline__ ull fma2(ull a, ull b, ull c) {
    ull d;
    asm("fma.rn.f32x2 %0, %1, %2, %3;" : "=l"(d) : "l"(a), "l"(b), "l"(c));
    return d;
}
__device__ __forceinline__ void unpack2(ull p, float& lo, float& hi) {
    unsigned a, b;
    asm("mov.b64 {%0, %1}, %2;" : "=r"(a), "=r"(b) : "l"(p));
    lo = __uint_as_float(a);
    hi = __uint_as_float(b);
}

// ---------------------------------------------------------------------------
// Shared memory layout (float offsets). Total 55904 floats = 223616 B.
// h3T aliases the h1T region (h1T dead after layer 2).
// ---------------------------------------------------------------------------
#define SM_W2 0
#define SM_W3 32768
#define SM_W4 40960
#define SM_B2 41600
#define SM_B3 41728
#define SM_B4 41792
#define SM_QP 41808
#define SM_CLS 42064
#define SM_H2T 42080
#define SM_H1T 46688
#define SM_TOTAL_BYTES (55904 * 4)

__global__ void __launch_bounds__(256, 1)
main_kernel(const float* __restrict__ W2, const float* __restrict__ b2,
            const float* __restrict__ W3, const float* __restrict__ b3,
            const float* __restrict__ W4, const float* __restrict__ b4,
            float* __restrict__ out) {
    extern __shared__ float sm[];
    float* W2s = sm + SM_W2;
    float* W3s = sm + SM_W3;
    float* W4s = sm + SM_W4;
    float* b2s = sm + SM_B2;
    float* b3s = sm + SM_B3;
    float* b4s = sm + SM_B4;
    float* qp  = sm + SM_QP;
    float* cls = sm + SM_CLS;
    float* h2T = sm + SM_H2T;  // [128][36] n-major
    float* h1T = sm + SM_H1T;  // [256][36] k-major
    float* h3T = sm + SM_H1T;  // [64][36] alias

    int tid = threadIdx.x;
    int lane = tid & 31, warp = tid >> 5;
    int q = blockIdx.x;

    // ---- stage weights / biases / qproj ----
    {
        float4* dst = (float4*)W2s;
        const float4* src = (const float4*)W2;
        for (int i = tid; i < 32768 / 4; i += 256) dst[i] = src[i];
        float4* d3 = (float4*)W3s;
        const float4* s3 = (const float4*)W3;
        for (int i = tid; i < 8192 / 4; i += 256) d3[i] = s3[i];
        for (int i = tid; i < 640; i += 256) W4s[i] = W4[i];
        if (tid < 128) b2s[tid] = b2[tid];
        if (tid < 64) b3s[tid] = b3[tid];
        if (tid < 10) b4s[tid] = b4[tid];
        if (tid < 16) cls[tid] = 0.f;
        qp[tid] = g_qproj[q * H0 + tid];
    }
    __syncthreads();

    int wm = warp >> 2;     // 0..1  m-warp
    int wn = warp & 3;      // 0..3  n-warp
    int li = lane >> 3;     // 0..3  m-sub
    int lj = lane & 7;      // 0..7  n-sub

    for (int t = 0; t < 5; t++) {
        int r0 = t * 32;

        // ---- build h1T[k][m] = relu(qproj[k] + iproj[r0+m][k]) ----
        {
            float qv = qp[tid];
            const float* ip = g_iproj + r0 * H0 + tid;
#pragma unroll
            for (int m = 0; m < 32; m++) {
                float v = qv + ip[m * H0];
                h1T[tid * 36 + m] = fmaxf(v, 0.f);
            }
        }
        __syncthreads();

        // ---- layer 2: [32,256] @ [256,128] ----
        {
            int mb = wm * 16 + li * 4;
            int nb = wn * 32 + lj * 4;
            const float4* A = (const float4*)(h1T + mb);          // stride 9 f4/k
            const ulonglong2* B = (const ulonglong2*)(W2s + nb);  // stride 32 u2/k
            ull acc[4][2];
#pragma unroll
            for (int m = 0; m < 4; m++) { acc[m][0] = 0ULL; acc[m][1] = 0ULL; }
#pragma unroll 4
            for (int k = 0; k < 256; k++) {
                float4 a = A[k * 9];
                ulonglong2 bv = B[k * 32];
                ull a0 = pack2(a.x), a1 = pack2(a.y), a2 = pack2(a.z), a3 = pack2(a.w);
                acc[0][0] = fma2(a0, bv.x, acc[0][0]);
                acc[0][1] = fma2(a0, bv.y, acc[0][1]);
                acc[1][0] = fma2(a1, bv.x, acc[1][0]);
                acc[1][1] = fma2(a1, bv.y, acc[1][1]);
                acc[2][0] = fma2(a2, bv.x, acc[2][0]);
                acc[2][1] = fma2(a2, bv.y, acc[2][1]);
                acc[3][0] = fma2(a3, bv.x, acc[3][0]);
                acc[3][1] = fma2(a3, bv.y, acc[3][1]);
            }
#pragma unroll
            for (int m = 0; m < 4; m++) {
#pragma unroll
                for (int p = 0; p < 2; p++) {
                    float lo, hi;
                    unpack2(acc[m][p], lo, hi);
                    int n = nb + 2 * p;
                    int mm = mb + m;
                    h2T[n * 36 + mm] = fmaxf(lo + b2s[n], 0.f);
                    h2T[(n + 1) * 36 + mm] = fmaxf(hi + b2s[n + 1], 0.f);
                }
            }
        }
        __syncthreads();

        // ---- layer 3: [32,128] @ [128,64] ----
        {
            int mb = wm * 16 + li * 4;
            int nb = wn * 16 + lj * 2;
            const float4* A = (const float4*)(h2T + mb);  // stride 9 f4/k
            const ull* B = (const ull*)(W3s + nb);        // stride 32 u/k
            ull acc[4] = {0ULL, 0ULL, 0ULL, 0ULL};
#pragma unroll 4
            for (int k = 0; k < 128; k++) {
                float4 a = A[k * 9];
                ull bv = B[k * 32];
                acc[0] = fma2(pack2(a.x), bv, acc[0]);
                acc[1] = fma2(pack2(a.y), bv, acc[1]);
                acc[2] = fma2(pack2(a.z), bv, acc[2]);
                acc[3] = fma2(pack2(a.w), bv, acc[3]);
            }
#pragma unroll
            for (int m = 0; m < 4; m++) {
                float lo, hi;
                unpack2(acc[m], lo, hi);
                int mm = mb + m;
                h3T[nb * 36 + mm] = fmaxf(lo + b3s[nb], 0.f);
                h3T[(nb + 1) * 36 + mm] = fmaxf(hi + b3s[nb + 1], 0.f);
            }
        }
        __syncthreads();

        // ---- layer 4 + tanh + reduce: [32,64] @ [64,10] ----
        for (int idx = tid; idx < 320; idx += 256) {
            int r = idx / 10;
            int n = idx - 10 * r;
            float acc = b4s[n];
#pragma unroll
            for (int k = 0; k < 64; k++)
                acc = fmaf(h3T[k * 36 + r], W4s[k * 10 + n], acc);
            float v = tanhf(acc);
            int c = (r0 + r) >> 4;
            atomicAdd(&cls[c], v * 0.1f);
        }
        __syncthreads();
    }

    if (tid < 10) out[q * 10 + tid] = cls[tid];
}

// ---------------------------------------------------------------------------
extern "C" void kernel_launch(void* const* d_in, const int* in_sizes, int n_in,
                              void* d_out, int out_size) {
    const float* queries  = (const float*)d_in[0];
    const float* supports = (const float*)d_in[1];
    const float* W1 = (const float*)d_in[2];
    const float* b1 = (const float*)d_in[3];
    const float* W2 = (const float*)d_in[4];
    const float* b2 = (const float*)d_in[5];
    const float* W3 = (const float*)d_in[6];
    const float* b3 = (const float*)d_in[7];
    const float* W4 = (const float*)d_in[8];
    const float* b4 = (const float*)d_in[9];
    float* out = (float*)d_out;

    float* qproj;
    float* iproj;
    cudaGetSymbolAddress((void**)&qproj, g_qproj);
    cudaGetSymbolAddress((void**)&iproj, g_iproj);

    cudaFuncSetAttribute(main_kernel,
                         cudaFuncAttributeMaxDynamicSharedMemorySize,
                         SM_TOTAL_BYTES);

    // qproj = queries @ W1[0:256,:]        (no bias)
    proj_kernel<<<QN / 8, 256>>>(queries, QN, W1, nullptr, qproj);
    // iproj = supports @ W1[256:512,:] + b1
    proj_kernel<<<RN / 8, 256>>>(supports, RN, W1 + 256 * H0, b1, iproj);
    // fused MLP + reduction, one block per query
    main_kernel<<<QN, 256, SM_TOTAL_BYTES>>>(W2, b2, W3, b3, W4, b4, out);
}

// round 7
// speedup vs baseline: 3.8040x; 3.8040x over previous
#include <cuda_runtime.h>
#include <math.h>

#define QN 2048
#define DN 256
#define RN 160
#define H0 256

__device__ float g_qproj[QN * H0];
__device__ float g_iproj[RN * H0];

// ---------------------------------------------------------------------------
// helpers
// ---------------------------------------------------------------------------
__device__ __forceinline__ unsigned f2tf(float f) {
    unsigned u;
    asm("cvt.rna.tf32.f32 %0, %1;" : "=r"(u) : "f"(f));
    return u;
}
__device__ __forceinline__ float tfr(float f) { return __uint_as_float(f2tf(f)); }

__device__ __forceinline__ void mma8(float* d, const unsigned* a, const unsigned* b) {
    asm volatile(
        "mma.sync.aligned.m16n8k8.row.col.f32.tf32.tf32.f32 "
        "{%0,%1,%2,%3}, {%4,%5,%6,%7}, {%8,%9}, {%0,%1,%2,%3};"
        : "+f"(d[0]), "+f"(d[1]), "+f"(d[2]), "+f"(d[3])
        : "r"(a[0]), "r"(a[1]), "r"(a[2]), "r"(a[3]), "r"(b[0]), "r"(b[1]));
}

// ---------------------------------------------------------------------------
// proj_mma: out[M,256] = A[M,256] @ W[256,256] (+bias), tf32 MMA.
// Fused launch: grid (18, 2). blockIdx.x < 16 -> queries->qproj;
// blockIdx.x >= 16 -> supports->iproj (W1 second half + b1).
// 512 threads. smem: As[128*260] + Wb[64*136].
// ---------------------------------------------------------------------------
#define PAS 260
#define PBS 136
#define PROJ_SMEM ((128 * PAS + 64 * PBS) * 4)

__global__ void __launch_bounds__(512, 1)
proj_mma(const float4* __restrict__ Q4, const float4* __restrict__ Sup4,
         const float* __restrict__ W1, const float* __restrict__ b1,
         float* __restrict__ qproj, float* __restrict__ iproj) {
    extern __shared__ float sm[];
    float* As = sm;
    float* Wb = sm + 128 * PAS;
    int tid = threadIdx.x, lane = tid & 31, warp = tid >> 5;
    int gid = lane >> 2, tig = lane & 3;

    const float4* A4;
    const float* Wsrc;
    const float* bias;
    float* outp;
    int Mrows, m0;
    if (blockIdx.x < 16) {
        A4 = Q4; Wsrc = W1; bias = nullptr; outp = qproj;
        Mrows = QN; m0 = blockIdx.x * 128;
    } else {
        A4 = Sup4; Wsrc = W1 + 256 * H0; bias = b1; outp = iproj;
        Mrows = RN; m0 = (blockIdx.x - 16) * 128;
    }
    int n0 = blockIdx.y * 128;

    // stage A tile (tf32-rounded), zero-pad OOB rows
    for (int idx = tid; idx < 128 * 64; idx += 512) {
        int m = idx >> 6, k4 = idx & 63;
        float4 v = make_float4(0.f, 0.f, 0.f, 0.f);
        if (m0 + m < Mrows) v = A4[(m0 + m) * 64 + k4];
        v.x = tfr(v.x); v.y = tfr(v.y); v.z = tfr(v.z); v.w = tfr(v.w);
        *(float4*)(As + m * PAS + k4 * 4) = v;
    }

    const float4* W4p = (const float4*)Wsrc;
    float4 pf[4];
#pragma unroll
    for (int i = 0; i < 4; i++) {
        int idx = tid + i * 512;
        int kk = idx >> 5, n4 = idx & 31;
        pf[i] = W4p[kk * 64 + (n0 >> 2) + n4];
    }

    int mb = (warp >> 2) * 32, nb = (warp & 3) * 32;
    float d[2][4][4];
#pragma unroll
    for (int a = 0; a < 2; a++)
#pragma unroll
        for (int b = 0; b < 4; b++)
#pragma unroll
            for (int c = 0; c < 4; c++) d[a][b][c] = 0.f;

    const float* A0 = As + (mb + gid) * PAS;
    const float* A1 = A0 + 8 * PAS;
    const float* A2 = A0 + 16 * PAS;
    const float* A3 = A0 + 24 * PAS;
    const float* Bb = Wb + nb + gid;

    for (int c = 0; c < 4; c++) {
        __syncthreads();
#pragma unroll
        for (int i = 0; i < 4; i++) {
            int idx = tid + i * 512;
            int kk = idx >> 5, n4 = idx & 31;
            float4 v = pf[i];
            v.x = tfr(v.x); v.y = tfr(v.y); v.z = tfr(v.z); v.w = tfr(v.w);
            *(float4*)(Wb + kk * PBS + n4 * 4) = v;
        }
        if (c < 3) {
#pragma unroll
            for (int i = 0; i < 4; i++) {
                int idx = tid + i * 512;
                int kk = idx >> 5, n4 = idx & 31;
                pf[i] = W4p[((c + 1) * 64 + kk) * 64 + (n0 >> 2) + n4];
            }
        }
        __syncthreads();
#pragma unroll
        for (int kk = 0; kk < 64; kk += 8) {
            int kg = c * 64 + kk;
            unsigned ua[2][4], ub[4][2];
            ua[0][0] = __float_as_uint(A0[kg + tig]);
            ua[0][1] = __float_as_uint(A1[kg + tig]);
            ua[0][2] = __float_as_uint(A0[kg + tig + 4]);
            ua[0][3] = __float_as_uint(A1[kg + tig + 4]);
            ua[1][0] = __float_as_uint(A2[kg + tig]);
            ua[1][1] = __float_as_uint(A3[kg + tig]);
            ua[1][2] = __float_as_uint(A2[kg + tig + 4]);
            ua[1][3] = __float_as_uint(A3[kg + tig + 4]);
#pragma unroll
            for (int ni = 0; ni < 4; ni++) {
                ub[ni][0] = __float_as_uint(Bb[(kk + tig) * PBS + ni * 8]);
                ub[ni][1] = __float_as_uint(Bb[(kk + tig + 4) * PBS + ni * 8]);
            }
#pragma unroll
            for (int mi = 0; mi < 2; mi++)
#pragma unroll
                for (int ni = 0; ni < 4; ni++) mma8(d[mi][ni], ua[mi], ub[ni]);
        }
    }

#pragma unroll
    for (int mi = 0; mi < 2; mi++) {
#pragma unroll
        for (int ni = 0; ni < 4; ni++) {
            int nl = n0 + nb + ni * 8 + tig * 2;
            float bn0 = bias ? bias[nl] : 0.f;
            float bn1 = bias ? bias[nl + 1] : 0.f;
            int mlo = m0 + mb + mi * 16 + gid, mhi = mlo + 8;
            if (mlo < Mrows) {
                outp[mlo * H0 + nl] = d[mi][ni][0] + bn0;
                outp[mlo * H0 + nl + 1] = d[mi][ni][1] + bn1;
            }
            if (mhi < Mrows) {
                outp[mhi * H0 + nl] = d[mi][ni][2] + bn0;
                outp[mhi * H0 + nl + 1] = d[mi][ni][3] + bn1;
            }
        }
    }
}

// ---------------------------------------------------------------------------
// main_mma: one block per query, 640 threads (20 warps).
// smem floats: h1[160*260]=41600 (h2[160*132] and h3[160*68] alias it),
//   Wb 9216, qp 256, b2 128, b3 64, b4p 16, W4s 1024, cls 16 -> 52320 fl.
// ---------------------------------------------------------------------------
#define S1 260
#define S2 132
#define S3 68
#define SW2 136
#define SW3 72
#define O_WB 41600
#define O_QP 50816
#define O_B2 51072
#define O_B3 51200
#define O_B4 51264
#define O_W4 51280
#define O_CLS 52304
#define MAIN_SMEM (52320 * 4)

__global__ void __launch_bounds__(640, 1)
main_mma(const float* __restrict__ W2, const float* __restrict__ b2,
         const float* __restrict__ W3, const float* __restrict__ b3,
         const float* __restrict__ W4, const float* __restrict__ b4,
         float* __restrict__ out) {
    extern __shared__ float sm[];
    float* h1 = sm;
    float* h2 = sm;
    float* h3 = sm + 21120;
    float* Wb = sm + O_WB;
    float* qp = sm + O_QP;
    float* b2s = sm + O_B2;
    float* b3s = sm + O_B3;
    float* b4s = sm + O_B4;
    float* W4s = sm + O_W4;
    float* cls = sm + O_CLS;

    int tid = threadIdx.x, lane = tid & 31, warp = tid >> 5;
    int gid = lane >> 2, tig = lane & 3;
    int q = blockIdx.x;

    // stage small operands
    if (tid < 64) ((float4*)qp)[tid] = ((const float4*)(g_qproj + q * H0))[tid];
    if (tid >= 64 && tid < 192) b2s[tid - 64] = b2[tid - 64];
    if (tid >= 192 && tid < 256) b3s[tid - 192] = b3[tid - 192];
    if (tid >= 256 && tid < 272) b4s[tid - 256] = (tid - 256 < 10) ? b4[tid - 256] : 0.f;
    if (tid >= 272 && tid < 288) cls[tid - 272] = 0.f;
    for (int idx = tid; idx < 1024; idx += 640) {
        int k = idx >> 4, nn = idx & 15;
        W4s[idx] = (nn < 10) ? W4[k * 10 + nn] : 0.f;
    }

    const float4* W24 = (const float4*)W2;
    float4 pf[4];
#pragma unroll
    for (int i = 0; i < 4; i++) {
        int idx = tid + i * 640;
        if (idx < 2048) {
            int kk = idx >> 5, n4 = idx & 31;
            pf[i] = W24[kk * 32 + n4];
        }
    }
    __syncthreads();

    // build h1 = tf32(relu(qproj[q] + iproj[item]))
    const float4* ip4 = (const float4*)g_iproj;
    const float4* qp4 = (const float4*)qp;
    for (int idx = tid; idx < 160 * 64; idx += 640) {
        int m = idx >> 6, k4 = idx & 63;
        float4 a = ip4[m * 64 + k4];
        float4 b = qp4[k4];
        float4 v;
        v.x = tfr(fmaxf(a.x + b.x, 0.f));
        v.y = tfr(fmaxf(a.y + b.y, 0.f));
        v.z = tfr(fmaxf(a.z + b.z, 0.f));
        v.w = tfr(fmaxf(a.w + b.w, 0.f));
        *(float4*)(h1 + m * S1 + k4 * 4) = v;
    }

    // ---------------- layer 2: [160,256] @ [256,128] ----------------
    int mb = (warp >> 2) * 32, nb = (warp & 3) * 32;
    float d[2][4][4];
#pragma unroll
    for (int a = 0; a < 2; a++)
#pragma unroll
        for (int b = 0; b < 4; b++)
#pragma unroll
            for (int c = 0; c < 4; c++) d[a][b][c] = 0.f;

    const float* A0 = h1 + (mb + gid) * S1;
    const float* A1 = A0 + 8 * S1;
    const float* A2 = A0 + 16 * S1;
    const float* A3 = A0 + 24 * S1;
    const float* Bb = Wb + nb + gid;

    for (int c = 0; c < 4; c++) {
        __syncthreads();
#pragma unroll
        for (int i = 0; i < 4; i++) {
            int idx = tid + i * 640;
            if (idx < 2048) {
                int kk = idx >> 5, n4 = idx & 31;
                float4 v = pf[i];
                v.x = tfr(v.x); v.y = tfr(v.y); v.z = tfr(v.z); v.w = tfr(v.w);
                *(float4*)(Wb + kk * SW2 + n4 * 4) = v;
            }
        }
        if (c < 3) {
#pragma unroll
            for (int i = 0; i < 4; i++) {
                int idx = tid + i * 640;
                if (idx < 2048) {
                    int kk = idx >> 5, n4 = idx & 31;
                    pf[i] = W24[((c + 1) * 64 + kk) * 32 + n4];
                }
            }
        }
        __syncthreads();
#pragma unroll
        for (int kk = 0; kk < 64; kk += 8) {
            int kg = c * 64 + kk;
            unsigned ua[2][4], ub[4][2];
            ua[0][0] = __float_as_uint(A0[kg + tig]);
            ua[0][1] = __float_as_uint(A1[kg + tig]);
            ua[0][2] = __float_as_uint(A0[kg + tig + 4]);
            ua[0][3] = __float_as_uint(A1[kg + tig + 4]);
            ua[1][0] = __float_as_uint(A2[kg + tig]);
            ua[1][1] = __float_as_uint(A3[kg + tig]);
            ua[1][2] = __float_as_uint(A2[kg + tig + 4]);
            ua[1][3] = __float_as_uint(A3[kg + tig + 4]);
#pragma unroll
            for (int ni = 0; ni < 4; ni++) {
                ub[ni][0] = __float_as_uint(Bb[(kk + tig) * SW2 + ni * 8]);
                ub[ni][1] = __float_as_uint(Bb[(kk + tig + 4) * SW2 + ni * 8]);
            }
#pragma unroll
            for (int mi = 0; mi < 2; mi++)
#pragma unroll
                for (int ni = 0; ni < 4; ni++) mma8(d[mi][ni], ua[mi], ub[ni]);
        }
    }
    __syncthreads();

    // layer-2 epilogue -> h2 (aliases h1); stage W3 into Wb
#pragma unroll
    for (int mi = 0; mi < 2; mi++) {
#pragma unroll
        for (int ni = 0; ni < 4; ni++) {
            int n = nb + ni * 8 + tig * 2;
            int mlo = mb + mi * 16 + gid, mhi = mlo + 8;
            h2[mlo * S2 + n] = tfr(fmaxf(d[mi][ni][0] + b2s[n], 0.f));
            h2[mlo * S2 + n + 1] = tfr(fmaxf(d[mi][ni][1] + b2s[n + 1], 0.f));
            h2[mhi * S2 + n] = tfr(fmaxf(d[mi][ni][2] + b2s[n], 0.f));
            h2[mhi * S2 + n + 1] = tfr(fmaxf(d[mi][ni][3] + b2s[n + 1], 0.f));
        }
    }
    const float4* W34 = (const float4*)W3;
    for (int idx = tid; idx < 2048; idx += 640) {
        int k = idx >> 4, n4 = idx & 15;
        float4 v = W34[k * 16 + n4];
        v.x = tfr(v.x); v.y = tfr(v.y); v.z = tfr(v.z); v.w = tfr(v.w);
        *(float4*)(Wb + k * SW3 + n4 * 4) = v;
    }
    __syncthreads();

    // ---------------- layer 3: [160,128] @ [128,64] ----------------
    int mb3 = (warp >> 1) * 16, nb3 = (warp & 1) * 32;
    float e[4][4];
#pragma unroll
    for (int b = 0; b < 4; b++)
#pragma unroll
        for (int c = 0; c < 4; c++) e[b][c] = 0.f;

    const float* C0 = h2 + (mb3 + gid) * S2;
    const float* C1 = C0 + 8 * S2;
    const float* Db = Wb + nb3 + gid;
#pragma unroll
    for (int k = 0; k < 128; k += 8) {
        unsigned ua[4], ub[4][2];
        ua[0] = __float_as_uint(C0[k + tig]);
        ua[1] = __float_as_uint(C1[k + tig]);
        ua[2] = __float_as_uint(C0[k + tig + 4]);
        ua[3] = __float_as_uint(C1[k + tig + 4]);
#pragma unroll
        for (int ni = 0; ni < 4; ni++) {
            ub[ni][0] = __float_as_uint(Db[(k + tig) * SW3 + ni * 8]);
            ub[ni][1] = __float_as_uint(Db[(k + tig + 4) * SW3 + ni * 8]);
        }
#pragma unroll
        for (int ni = 0; ni < 4; ni++) mma8(e[ni], ua, ub[ni]);
    }
    __syncthreads();

    // layer-3 epilogue -> h3
#pragma unroll
    for (int ni = 0; ni < 4; ni++) {
        int n = nb3 + ni * 8 + tig * 2;
        int mlo = mb3 + gid, mhi = mlo + 8;
        h3[mlo * S3 + n] = tfr(fmaxf(e[ni][0] + b3s[n], 0.f));
        h3[mlo * S3 + n + 1] = tfr(fmaxf(e[ni][1] + b3s[n + 1], 0.f));
        h3[mhi * S3 + n] = tfr(fmaxf(e[ni][2] + b3s[n], 0.f));
        h3[mhi * S3 + n + 1] = tfr(fmaxf(e[ni][3] + b3s[n + 1], 0.f));
    }
    __syncthreads();

    // ---------------- layer 4 + tanh + mean/sum reduction ----------------
#pragma unroll
    for (int it = 0; it < 4; it++) {
        int idx = tid + it * 640;
        int r = idx >> 4, nn = idx & 15;
        float acc = b4s[nn];
#pragma unroll 8
        for (int k = 0; k < 64; k++)
            acc = fmaf(h3[r * S3 + k], W4s[k * 16 + nn], acc);
        float v = tanhf(acc);  // nn>=10 lanes: acc==0 -> tanh 0
#pragma unroll
        for (int o = 8; o; o >>= 1) v += __shfl_xor_sync(0xffffffffu, v, o);
        if ((lane & 15) == 0) atomicAdd(&cls[r >> 4], 0.1f * v);
    }
    __syncthreads();
    if (tid < 10) out[q * 10 + tid] = cls[tid];
}

// ---------------------------------------------------------------------------
extern "C" void kernel_launch(void* const* d_in, const int* in_sizes, int n_in,
                              void* d_out, int out_size) {
    const float* queries  = (const float*)d_in[0];
    const float* supports = (const float*)d_in[1];
    const float* W1 = (const float*)d_in[2];
    const float* b1 = (const float*)d_in[3];
    const float* W2 = (const float*)d_in[4];
    const float* b2 = (const float*)d_in[5];
    const float* W3 = (const float*)d_in[6];
    const float* b3 = (const float*)d_in[7];
    const float* W4 = (const float*)d_in[8];
    const float* b4 = (const float*)d_in[9];
    float* out = (float*)d_out;

    float* qproj;
    float* iproj;
    cudaGetSymbolAddress((void**)&qproj, g_qproj);
    cudaGetSymbolAddress((void**)&iproj, g_iproj);

    cudaFuncSetAttribute(proj_mma, cudaFuncAttributeMaxDynamicSharedMemorySize, PROJ_SMEM);
    cudaFuncSetAttribute(main_mma, cudaFuncAttributeMaxDynamicSharedMemorySize, MAIN_SMEM);

    // fused: qproj = queries @ W1[0:256,:]; iproj = supports @ W1[256:,:] + b1
    proj_mma<<<dim3(18, 2), 512, PROJ_SMEM>>>(
        (const float4*)queries, (const float4*)supports, W1, b1, qproj, iproj);
    // fused MLP + reduction
    main_mma<<<QN, 640, MAIN_SMEM>>>(W2, b2, W3, b3, W4, b4, out);
}

// round 10
// speedup vs baseline: 5.2454x; 1.3789x over previous
#include <cuda_runtime.h>
#include <cuda_fp16.h>
#include <math.h>

#define QN 2048
#define DN 256
#define RN 160
#define H0 256

__device__ float g_qproj[QN * H0];
__device__ float g_iproj[RN * H0];
__device__ unsigned g_w2h[128 * 132];  // W2 as half2 words, [n][k2] stride 132
__device__ unsigned g_w3h[64 * 68];    // W3 as half2 words, [n][k2] stride 68

// ---------------------------------------------------------------------------
// helpers
// ---------------------------------------------------------------------------
__device__ __forceinline__ unsigned f2tf(float f) {
    unsigned u;
    asm("cvt.rna.tf32.f32 %0, %1;" : "=r"(u) : "f"(f));
    return u;
}
__device__ __forceinline__ float tfr(float f) { return __uint_as_float(f2tf(f)); }

__device__ __forceinline__ void mma8(float* d, const unsigned* a, const unsigned* b) {
    asm volatile(
        "mma.sync.aligned.m16n8k8.row.col.f32.tf32.tf32.f32 "
        "{%0,%1,%2,%3}, {%4,%5,%6,%7}, {%8,%9}, {%0,%1,%2,%3};"
        : "+f"(d[0]), "+f"(d[1]), "+f"(d[2]), "+f"(d[3])
        : "r"(a[0]), "r"(a[1]), "r"(a[2]), "r"(a[3]), "r"(b[0]), "r"(b[1]));
}

__device__ __forceinline__ void mma16(float* d, const unsigned* a, const unsigned* b) {
    asm volatile(
        "mma.sync.aligned.m16n8k16.row.col.f32.f16.f16.f32 "
        "{%0,%1,%2,%3}, {%4,%5,%6,%7}, {%8,%9}, {%0,%1,%2,%3};"
        : "+f"(d[0]), "+f"(d[1]), "+f"(d[2]), "+f"(d[3])
        : "r"(a[0]), "r"(a[1]), "r"(a[2]), "r"(a[3]), "r"(b[0]), "r"(b[1]));
}

__device__ __forceinline__ unsigned h2u(__half2 h) {
    unsigned u;
    __builtin_memcpy(&u, &h, 4);
    return u;
}

// ---------------------------------------------------------------------------
// prep_w: transpose+convert W2 [256k,128n] and W3 [128k,64n] to half2 images
// g_w2h[n*132 + k2] = (W2[2k2][n], W2[2k2+1][n]); likewise g_w3h stride 68.
// grid 80 x 256 covers 128*128 + 64*64 = 20480 words.
// ---------------------------------------------------------------------------
__global__ void prep_w(const float* __restrict__ W2, const float* __restrict__ W3) {
    int idx = blockIdx.x * blockDim.x + threadIdx.x;
    if (idx < 128 * 128) {
        int k2 = idx >> 7, n = idx & 127;
        __half2 h = __floats2half2_rn(W2[(2 * k2) * 128 + n], W2[(2 * k2 + 1) * 128 + n]);
        g_w2h[n * 132 + k2] = h2u(h);
    } else if (idx < 128 * 128 + 64 * 64) {
        int j = idx - 128 * 128;
        int k2 = j >> 6, n = j & 63;
        __half2 h = __floats2half2_rn(W3[(2 * k2) * 64 + n], W3[(2 * k2 + 1) * 64 + n]);
        g_w3h[n * 68 + k2] = h2u(h);
    }
}

// ---------------------------------------------------------------------------
// proj_mma: unchanged from R7 (tf32). out[M,256] = A[M,256] @ W[256,256](+bias)
// ---------------------------------------------------------------------------
#define PAS 260
#define PBS 136
#define PROJ_SMEM ((128 * PAS + 64 * PBS) * 4)

__global__ void __launch_bounds__(512, 1)
proj_mma(const float4* __restrict__ Q4, const float4* __restrict__ Sup4,
         const float* __restrict__ W1, const float* __restrict__ b1,
         float* __restrict__ qproj, float* __restrict__ iproj) {
    extern __shared__ float sm[];
    float* As = sm;
    float* Wb = sm + 128 * PAS;
    int tid = threadIdx.x, lane = tid & 31, warp = tid >> 5;
    int gid = lane >> 2, tig = lane & 3;

    const float4* A4;
    const float* Wsrc;
    const float* bias;
    float* outp;
    int Mrows, m0;
    if (blockIdx.x < 16) {
        A4 = Q4; Wsrc = W1; bias = nullptr; outp = qproj;
        Mrows = QN; m0 = blockIdx.x * 128;
    } else {
        A4 = Sup4; Wsrc = W1 + 256 * H0; bias = b1; outp = iproj;
        Mrows = RN; m0 = (blockIdx.x - 16) * 128;
    }
    int n0 = blockIdx.y * 128;

    for (int idx = tid; idx < 128 * 64; idx += 512) {
        int m = idx >> 6, k4 = idx & 63;
        float4 v = make_float4(0.f, 0.f, 0.f, 0.f);
        if (m0 + m < Mrows) v = A4[(m0 + m) * 64 + k4];
        v.x = tfr(v.x); v.y = tfr(v.y); v.z = tfr(v.z); v.w = tfr(v.w);
        *(float4*)(As + m * PAS + k4 * 4) = v;
    }

    const float4* W4p = (const float4*)Wsrc;
    float4 pf[4];
#pragma unroll
    for (int i = 0; i < 4; i++) {
        int idx = tid + i * 512;
        int kk = idx >> 5, n4 = idx & 31;
        pf[i] = W4p[kk * 64 + (n0 >> 2) + n4];
    }

    int mb = (warp >> 2) * 32, nb = (warp & 3) * 32;
    float d[2][4][4];
#pragma unroll
    for (int a = 0; a < 2; a++)
#pragma unroll
        for (int b = 0; b < 4; b++)
#pragma unroll
            for (int c = 0; c < 4; c++) d[a][b][c] = 0.f;

    const float* A0 = As + (mb + gid) * PAS;
    const float* A1 = A0 + 8 * PAS;
    const float* A2 = A0 + 16 * PAS;
    const float* A3 = A0 + 24 * PAS;
    const float* Bb = Wb + nb + gid;

    for (int c = 0; c < 4; c++) {
        __syncthreads();
#pragma unroll
        for (int i = 0; i < 4; i++) {
            int idx = tid + i * 512;
            int kk = idx >> 5, n4 = idx & 31;
            float4 v = pf[i];
            v.x = tfr(v.x); v.y = tfr(v.y); v.z = tfr(v.z); v.w = tfr(v.w);
            *(float4*)(Wb + kk * PBS + n4 * 4) = v;
        }
        if (c < 3) {
#pragma unroll
            for (int i = 0; i < 4; i++) {
                int idx = tid + i * 512;
                int kk = idx >> 5, n4 = idx & 31;
                pf[i] = W4p[((c + 1) * 64 + kk) * 64 + (n0 >> 2) + n4];
            }
        }
        __syncthreads();
#pragma unroll
        for (int kk = 0; kk < 64; kk += 8) {
            int kg = c * 64 + kk;
            unsigned ua[2][4], ub[4][2];
            ua[0][0] = __float_as_uint(A0[kg + tig]);
            ua[0][1] = __float_as_uint(A1[kg + tig]);
            ua[0][2] = __float_as_uint(A0[kg + tig + 4]);
            ua[0][3] = __float_as_uint(A1[kg + tig + 4]);
            ua[1][0] = __float_as_uint(A2[kg + tig]);
            ua[1][1] = __float_as_uint(A3[kg + tig]);
            ua[1][2] = __float_as_uint(A2[kg + tig + 4]);
            ua[1][3] = __float_as_uint(A3[kg + tig + 4]);
#pragma unroll
            for (int ni = 0; ni < 4; ni++) {
                ub[ni][0] = __float_as_uint(Bb[(kk + tig) * PBS + ni * 8]);
                ub[ni][1] = __float_as_uint(Bb[(kk + tig + 4) * PBS + ni * 8]);
            }
#pragma unroll
            for (int mi = 0; mi < 2; mi++)
#pragma unroll
                for (int ni = 0; ni < 4; ni++) mma8(d[mi][ni], ua[mi], ub[ni]);
        }
    }

#pragma unroll
    for (int mi = 0; mi < 2; mi++) {
#pragma unroll
        for (int ni = 0; ni < 4; ni++) {
            int nl = n0 + nb + ni * 8 + tig * 2;
            float bn0 = bias ? bias[nl] : 0.f;
            float bn1 = bias ? bias[nl + 1] : 0.f;
            int mlo = m0 + mb + mi * 16 + gid, mhi = mlo + 8;
            if (mlo < Mrows) {
                outp[mlo * H0 + nl] = d[mi][ni][0] + bn0;
                outp[mlo * H0 + nl + 1] = d[mi][ni][1] + bn1;
            }
            if (mhi < Mrows) {
                outp[mhi * H0 + nl] = d[mi][ni][2] + bn0;
                outp[mhi * H0 + nl + 1] = d[mi][ni][3] + bn1;
            }
        }
    }
}

// ---------------------------------------------------------------------------
// main_mma: one block per query, 640 threads. fp16 MMA (m16n8k16) layers 2/3.
// smem bytes:
//   [0,84480)        h1w: half2 words [160 m][132 k2-stride]  (h2w aliases, 43520)
//   [84480,152064)   w2s: half2 words [128 n][132]            (h3f aliases, 43520)
//   [152064,169472)  w3s: half2 words [64 n][68]
//   [169472,173568)  W4s f32 [64][16]
//   [173568,174592)  qp f32 [256]
//   [174592,175104)  b2s[128]   [175104,175360) b3s[64]
//   [175360,175424)  b4s[16]    [175424,175488) cls[16]
// ---------------------------------------------------------------------------
#define MAIN_SMEM 175488

__global__ void __launch_bounds__(640, 1)
main_mma(const float* __restrict__ b2, const float* __restrict__ b3,
         const float* __restrict__ W4, const float* __restrict__ b4,
         float* __restrict__ out) {
    extern __shared__ char smc[];
    unsigned* h1w = (unsigned*)(smc);
    unsigned* h2w = (unsigned*)(smc);
    unsigned* w2s = (unsigned*)(smc + 84480);
    float* h3f = (float*)(smc + 84480);
    unsigned* w3s = (unsigned*)(smc + 152064);
    float* W4s = (float*)(smc + 169472);
    float* qp  = (float*)(smc + 173568);
    float* b2s = (float*)(smc + 174592);
    float* b3s = (float*)(smc + 175104);
    float* b4s = (float*)(smc + 175360);
    float* cls = (float*)(smc + 175424);

    int tid = threadIdx.x, lane = tid & 31, warp = tid >> 5;
    int gid = lane >> 2, tig = lane & 3;
    int q = blockIdx.x;

    // ---- stage: weights (pure coalesced copy of prepped images) + misc ----
    {
        const uint4* s2 = (const uint4*)g_w2h;
        uint4* d2 = (uint4*)w2s;
        for (int i = tid; i < 4224; i += 640) d2[i] = s2[i];
        const uint4* s3 = (const uint4*)g_w3h;
        uint4* d3 = (uint4*)w3s;
        for (int i = tid; i < 1088; i += 640) d3[i] = s3[i];
        for (int idx = tid; idx < 1024; idx += 640) {
            int k = idx >> 4, nn = idx & 15;
            W4s[idx] = (nn < 10) ? W4[k * 10 + nn] : 0.f;
        }
        if (tid < 64) ((float4*)qp)[tid] = ((const float4*)(g_qproj + q * H0))[tid];
        if (tid >= 64 && tid < 192) b2s[tid - 64] = b2[tid - 64];
        if (tid >= 192 && tid < 256) b3s[tid - 192] = b3[tid - 192];
        if (tid >= 256 && tid < 272) b4s[tid - 256] = (tid - 256 < 10) ? b4[tid - 256] : 0.f;
        if (tid >= 272 && tid < 288) cls[tid - 272] = 0.f;
    }
    __syncthreads();

    // ---- build h1 = fp16(relu(qproj[q] + iproj[item])), [m][k] half ----
    {
        const float4* ip4 = (const float4*)g_iproj;
        const float4* qp4 = (const float4*)qp;
        for (int idx = tid; idx < 160 * 64; idx += 640) {
            int m = idx >> 6, k4 = idx & 63;
            float4 a = ip4[m * 64 + k4];
            float4 b = qp4[k4];
            __half2 lo = __floats2half2_rn(fmaxf(a.x + b.x, 0.f), fmaxf(a.y + b.y, 0.f));
            __half2 hi = __floats2half2_rn(fmaxf(a.z + b.z, 0.f), fmaxf(a.w + b.w, 0.f));
            h1w[m * 132 + 2 * k4] = h2u(lo);
            h1w[m * 132 + 2 * k4 + 1] = h2u(hi);
        }
    }
    __syncthreads();

    // ---------------- layer 2: [160,256] @ [256,128], fp16 k16 ----------------
    int mb = (warp >> 2) * 32, nb = (warp & 3) * 32;
    float d[2][4][4];
#pragma unroll
    for (int a = 0; a < 2; a++)
#pragma unroll
        for (int b = 0; b < 4; b++)
#pragma unroll
            for (int c = 0; c < 4; c++) d[a][b][c] = 0.f;

    {
        const unsigned* A0 = h1w + (mb + gid) * 132;
        const unsigned* Bb = w2s + (nb + gid) * 132;
#pragma unroll 4
        for (int k2 = 0; k2 < 128; k2 += 8) {
            unsigned ua[2][4], ub[4][2];
            ua[0][0] = A0[k2 + tig];
            ua[0][1] = A0[8 * 132 + k2 + tig];
            ua[0][2] = A0[k2 + tig + 4];
            ua[0][3] = A0[8 * 132 + k2 + tig + 4];
            ua[1][0] = A0[16 * 132 + k2 + tig];
            ua[1][1] = A0[24 * 132 + k2 + tig];
            ua[1][2] = A0[16 * 132 + k2 + tig + 4];
            ua[1][3] = A0[24 * 132 + k2 + tig + 4];
#pragma unroll
            for (int ni = 0; ni < 4; ni++) {
                ub[ni][0] = Bb[ni * 8 * 132 + k2 + tig];
                ub[ni][1] = Bb[ni * 8 * 132 + k2 + tig + 4];
            }
#pragma unroll
            for (int mi = 0; mi < 2; mi++)
#pragma unroll
                for (int ni = 0; ni < 4; ni++) mma16(d[mi][ni], ua[mi], ub[ni]);
        }
    }
    __syncthreads();

    // layer-2 epilogue -> h2 (half2 words, aliases h1)
#pragma unroll
    for (int mi = 0; mi < 2; mi++) {
#pragma unroll
        for (int ni = 0; ni < 4; ni++) {
            int n = nb + ni * 8 + tig * 2;
            int w = ((nb + ni * 8) >> 1) + tig;
            int mlo = mb + mi * 16 + gid, mhi = mlo + 8;
            __half2 vlo = __floats2half2_rn(fmaxf(d[mi][ni][0] + b2s[n], 0.f),
                                            fmaxf(d[mi][ni][1] + b2s[n + 1], 0.f));
            __half2 vhi = __floats2half2_rn(fmaxf(d[mi][ni][2] + b2s[n], 0.f),
                                            fmaxf(d[mi][ni][3] + b2s[n + 1], 0.f));
            h2w[mlo * 68 + w] = h2u(vlo);
            h2w[mhi * 68 + w] = h2u(vhi);
        }
    }
    __syncthreads();

    // ---------------- layer 3: [160,128] @ [128,64], fp16 k16 ----------------
    int mb3 = (warp >> 1) * 16, nb3 = (warp & 1) * 32;
    float e[4][4];
#pragma unroll
    for (int b = 0; b < 4; b++)
#pragma unroll
        for (int c = 0; c < 4; c++) e[b][c] = 0.f;

    {
        const unsigned* C0 = h2w + (mb3 + gid) * 68;
        const unsigned* Db = w3s + (nb3 + gid) * 68;
#pragma unroll 4
        for (int k2 = 0; k2 < 64; k2 += 8) {
            unsigned ua[4], ub[4][2];
            ua[0] = C0[k2 + tig];
            ua[1] = C0[8 * 68 + k2 + tig];
            ua[2] = C0[k2 + tig + 4];
            ua[3] = C0[8 * 68 + k2 + tig + 4];
#pragma unroll
            for (int ni = 0; ni < 4; ni++) {
                ub[ni][0] = Db[ni * 8 * 68 + k2 + tig];
                ub[ni][1] = Db[ni * 8 * 68 + k2 + tig + 4];
            }
#pragma unroll
            for (int ni = 0; ni < 4; ni++) mma16(e[ni], ua, ub[ni]);
        }
    }

    // layer-3 epilogue -> h3 (f32, lives in dead w2s region; no race with h2/w3 reads)
#pragma unroll
    for (int ni = 0; ni < 4; ni++) {
        int n = nb3 + ni * 8 + tig * 2;
        int mlo = mb3 + gid, mhi = mlo + 8;
        h3f[mlo * 68 + n] = fmaxf(e[ni][0] + b3s[n], 0.f);
        h3f[mlo * 68 + n + 1] = fmaxf(e[ni][1] + b3s[n + 1], 0.f);
        h3f[mhi * 68 + n] = fmaxf(e[ni][2] + b3s[n], 0.f);
        h3f[mhi * 68 + n + 1] = fmaxf(e[ni][3] + b3s[n + 1], 0.f);
    }
    __syncthreads();

    // ---------------- layer 4 + tanh + mean/sum reduction ----------------
#pragma unroll
    for (int it = 0; it < 4; it++) {
        int idx = tid + it * 640;
        int r = idx >> 4, nn = idx & 15;
        float acc = b4s[nn];
#pragma unroll 8
        for (int k = 0; k < 64; k++)
            acc = fmaf(h3f[r * 68 + k], W4s[k * 16 + nn], acc);
        float v = tanhf(acc);
#pragma unroll
        for (int o = 8; o; o >>= 1) v += __shfl_xor_sync(0xffffffffu, v, o);
        if ((lane & 15) == 0) atomicAdd(&cls[r >> 4], 0.1f * v);
    }
    __syncthreads();
    if (tid < 10) out[q * 10 + tid] = cls[tid];
}

// ---------------------------------------------------------------------------
extern "C" void kernel_launch(void* const* d_in, const int* in_sizes, int n_in,
                              void* d_out, int out_size) {
    const float* queries  = (const float*)d_in[0];
    const float* supports = (const float*)d_in[1];
    const float* W1 = (const float*)d_in[2];
    const float* b1 = (const float*)d_in[3];
    const float* W2 = (const float*)d_in[4];
    const float* b2 = (const float*)d_in[5];
    const float* W3 = (const float*)d_in[6];
    const float* b3 = (const float*)d_in[7];
    const float* W4 = (const float*)d_in[8];
    const float* b4 = (const float*)d_in[9];
    float* out = (float*)d_out;

    float* qproj;
    float* iproj;
    cudaGetSymbolAddress((void**)&qproj, g_qproj);
    cudaGetSymbolAddress((void**)&iproj, g_iproj);

    cudaFuncSetAttribute(proj_mma, cudaFuncAttributeMaxDynamicSharedMemorySize, PROJ_SMEM);
    cudaFuncSetAttribute(main_mma, cudaFuncAttributeMaxDynamicSharedMemorySize, MAIN_SMEM);

    // qproj/iproj (tf32) and fp16 weight images
    proj_mma<<<dim3(18, 2), 512, PROJ_SMEM>>>(
        (const float4*)queries, (const float4*)supports, W1, b1, qproj, iproj);
    prep_w<<<80, 256>>>(W2, W3);
    // fused MLP + reduction
    main_mma<<<QN, 640, MAIN_SMEM>>>(b2, b3, W4, b4, out);
}

// round 13
// speedup vs baseline: 5.4479x; 1.0386x over previous
#include <cuda_runtime.h>
#include <cuda_fp16.h>
#include <math.h>

#define QN 2048
#define DN 256
#define RN 160
#define H0 256

__device__ float g_qproj[QN * H0];
__device__ float g_iproj[RN * H0];
__device__ unsigned g_w2h[128 * 132];  // W2 as half2 words, [n][k2] stride 132
__device__ unsigned g_w3h[64 * 68];    // W3 as half2 words, [n][k2] stride 68

// ---------------------------------------------------------------------------
// helpers
// ---------------------------------------------------------------------------
__device__ __forceinline__ unsigned f2tf(float f) {
    unsigned u;
    asm("cvt.rna.tf32.f32 %0, %1;" : "=r"(u) : "f"(f));
    return u;
}
__device__ __forceinline__ float tfr(float f) { return __uint_as_float(f2tf(f)); }

__device__ __forceinline__ void mma8(float* d, const unsigned* a, const unsigned* b) {
    asm volatile(
        "mma.sync.aligned.m16n8k8.row.col.f32.tf32.tf32.f32 "
        "{%0,%1,%2,%3}, {%4,%5,%6,%7}, {%8,%9}, {%0,%1,%2,%3};"
        : "+f"(d[0]), "+f"(d[1]), "+f"(d[2]), "+f"(d[3])
        : "r"(a[0]), "r"(a[1]), "r"(a[2]), "r"(a[3]), "r"(b[0]), "r"(b[1]));
}

__device__ __forceinline__ void mma16(float* d, const unsigned* a, const unsigned* b) {
    asm volatile(
        "mma.sync.aligned.m16n8k16.row.col.f32.f16.f16.f32 "
        "{%0,%1,%2,%3}, {%4,%5,%6,%7}, {%8,%9}, {%0,%1,%2,%3};"
        : "+f"(d[0]), "+f"(d[1]), "+f"(d[2]), "+f"(d[3])
        : "r"(a[0]), "r"(a[1]), "r"(a[2]), "r"(a[3]), "r"(b[0]), "r"(b[1]));
}

__device__ __forceinline__ void ldsm4(unsigned* r, unsigned addr) {
    asm volatile(
        "ldmatrix.sync.aligned.m8n8.x4.shared.b16 {%0,%1,%2,%3}, [%4];"
        : "=r"(r[0]), "=r"(r[1]), "=r"(r[2]), "=r"(r[3]) : "r"(addr));
}

__device__ __forceinline__ unsigned sm_u32(const void* p) {
    return (unsigned)__cvta_generic_to_shared(p);
}

__device__ __forceinline__ unsigned h2u(__half2 h) {
    unsigned u;
    __builtin_memcpy(&u, &h, 4);
    return u;
}

// ---------------------------------------------------------------------------
// prep_w: transpose+convert W2 [256k,128n] and W3 [128k,64n] to half2 images
// ---------------------------------------------------------------------------
__global__ void prep_w(const float* __restrict__ W2, const float* __restrict__ W3) {
    int idx = blockIdx.x * blockDim.x + threadIdx.x;
    if (idx < 128 * 128) {
        int k2 = idx >> 7, n = idx & 127;
        __half2 h = __floats2half2_rn(W2[(2 * k2) * 128 + n], W2[(2 * k2 + 1) * 128 + n]);
        g_w2h[n * 132 + k2] = h2u(h);
    } else if (idx < 128 * 128 + 64 * 64) {
        int j = idx - 128 * 128;
        int k2 = j >> 6, n = j & 63;
        __half2 h = __floats2half2_rn(W3[(2 * k2) * 64 + n], W3[(2 * k2 + 1) * 64 + n]);
        g_w3h[n * 68 + k2] = h2u(h);
    }
}

// ---------------------------------------------------------------------------
// proj_mma: out[M,256] = A[M,256] @ W[256,256] (+bias), tf32 MMA.
// RETILED: M=64 per block, 256 threads (8 warps). grid (35, 2):
// bx < 32 -> queries tile bx; bx >= 32 -> supports tile (bx-32).
// smem: As[64*260] + Wb[64*136] = 101376 B.
// ---------------------------------------------------------------------------
#define PAS 260
#define PBS 136
#define PROJ_SMEM ((64 * PAS + 64 * PBS) * 4)

__global__ void __launch_bounds__(256, 1)
proj_mma(const float4* __restrict__ Q4, const float4* __restrict__ Sup4,
         const float* __restrict__ W1, const float* __restrict__ b1,
         float* __restrict__ qproj, float* __restrict__ iproj) {
    extern __shared__ float sm[];
    float* As = sm;
    float* Wb = sm + 64 * PAS;
    int tid = threadIdx.x, lane = tid & 31, warp = tid >> 5;
    int gid = lane >> 2, tig = lane & 3;

    const float4* A4;
    const float* Wsrc;
    const float* bias;
    float* outp;
    int Mrows, m0;
    if (blockIdx.x < 32) {
        A4 = Q4; Wsrc = W1; bias = nullptr; outp = qproj;
        Mrows = QN; m0 = blockIdx.x * 64;
    } else {
        A4 = Sup4; Wsrc = W1 + 256 * H0; bias = b1; outp = iproj;
        Mrows = RN; m0 = (blockIdx.x - 32) * 64;
    }
    int n0 = blockIdx.y * 128;

    // stage A tile (tf32-rounded), zero-pad OOB rows
    for (int idx = tid; idx < 64 * 64; idx += 256) {
        int m = idx >> 6, k4 = idx & 63;
        float4 v = make_float4(0.f, 0.f, 0.f, 0.f);
        if (m0 + m < Mrows) v = A4[(m0 + m) * 64 + k4];
        v.x = tfr(v.x); v.y = tfr(v.y); v.z = tfr(v.z); v.w = tfr(v.w);
        *(float4*)(As + m * PAS + k4 * 4) = v;
    }

    const float4* W4p = (const float4*)Wsrc;
    float4 pf[8];
#pragma unroll
    for (int i = 0; i < 8; i++) {
        int idx = tid + i * 256;
        int kk = idx >> 5, n4 = idx & 31;
        pf[i] = W4p[kk * 64 + (n0 >> 2) + n4];
    }

    int mb = (warp >> 2) * 32, nb = (warp & 3) * 32;
    float d[2][4][4];
#pragma unroll
    for (int a = 0; a < 2; a++)
#pragma unroll
        for (int b = 0; b < 4; b++)
#pragma unroll
            for (int c = 0; c < 4; c++) d[a][b][c] = 0.f;

    const float* A0 = As + (mb + gid) * PAS;
    const float* A1 = A0 + 8 * PAS;
    const float* A2 = A0 + 16 * PAS;
    const float* A3 = A0 + 24 * PAS;
    const float* Bb = Wb + nb + gid;

    for (int c = 0; c < 4; c++) {
        __syncthreads();
#pragma unroll
        for (int i = 0; i < 8; i++) {
            int idx = tid + i * 256;
            int kk = idx >> 5, n4 = idx & 31;
            float4 v = pf[i];
            v.x = tfr(v.x); v.y = tfr(v.y); v.z = tfr(v.z); v.w = tfr(v.w);
            *(float4*)(Wb + kk * PBS + n4 * 4) = v;
        }
        if (c < 3) {
#pragma unroll
            for (int i = 0; i < 8; i++) {
                int idx = tid + i * 256;
                int kk = idx >> 5, n4 = idx & 31;
                pf[i] = W4p[((c + 1) * 64 + kk) * 64 + (n0 >> 2) + n4];
            }
        }
        __syncthreads();
#pragma unroll
        for (int kk = 0; kk < 64; kk += 8) {
            int kg = c * 64 + kk;
            unsigned ua[2][4], ub[4][2];
            ua[0][0] = __float_as_uint(A0[kg + tig]);
            ua[0][1] = __float_as_uint(A1[kg + tig]);
            ua[0][2] = __float_as_uint(A0[kg + tig + 4]);
            ua[0][3] = __float_as_uint(A1[kg + tig + 4]);
            ua[1][0] = __float_as_uint(A2[kg + tig]);
            ua[1][1] = __float_as_uint(A3[kg + tig]);
            ua[1][2] = __float_as_uint(A2[kg + tig + 4]);
            ua[1][3] = __float_as_uint(A3[kg + tig + 4]);
#pragma unroll
            for (int ni = 0; ni < 4; ni++) {
                ub[ni][0] = __float_as_uint(Bb[(kk + tig) * PBS + ni * 8]);
                ub[ni][1] = __float_as_uint(Bb[(kk + tig + 4) * PBS + ni * 8]);
            }
#pragma unroll
            for (int mi = 0; mi < 2; mi++)
#pragma unroll
                for (int ni = 0; ni < 4; ni++) mma8(d[mi][ni], ua[mi], ub[ni]);
        }
    }

#pragma unroll
    for (int mi = 0; mi < 2; mi++) {
#pragma unroll
        for (int ni = 0; ni < 4; ni++) {
            int nl = n0 + nb + ni * 8 + tig * 2;
            float bn0 = bias ? bias[nl] : 0.f;
            float bn1 = bias ? bias[nl + 1] : 0.f;
            int mlo = m0 + mb + mi * 16 + gid, mhi = mlo + 8;
            if (mlo < Mrows) {
                outp[mlo * H0 + nl] = d[mi][ni][0] + bn0;
                outp[mlo * H0 + nl + 1] = d[mi][ni][1] + bn1;
            }
            if (mhi < Mrows) {
                outp[mhi * H0 + nl] = d[mi][ni][2] + bn0;
                outp[mhi * H0 + nl + 1] = d[mi][ni][3] + bn1;
            }
        }
    }
}

// ---------------------------------------------------------------------------
// main_mma: one block per query, 640 threads. fp16 MMA + ldmatrix fragment
// loads. smem layout identical to R8 (see offsets).
// ---------------------------------------------------------------------------
#define MAIN_SMEM 175488

__global__ void __launch_bounds__(640, 1)
main_mma(const float* __restrict__ b2, const float* __restrict__ b3,
         const float* __restrict__ W4, const float* __restrict__ b4,
         float* __restrict__ out) {
    extern __shared__ char smc[];
    unsigned* h1w = (unsigned*)(smc);
    unsigned* h2w = (unsigned*)(smc);
    unsigned* w2s = (unsigned*)(smc + 84480);
    float* h3f = (float*)(smc + 84480);
    unsigned* w3s = (unsigned*)(smc + 152064);
    float* W4s = (float*)(smc + 169472);
    float* qp  = (float*)(smc + 173568);
    float* b2s = (float*)(smc + 174592);
    float* b3s = (float*)(smc + 175104);
    float* b4s = (float*)(smc + 175360);
    float* cls = (float*)(smc + 175424);

    int tid = threadIdx.x, lane = tid & 31, warp = tid >> 5;
    int gid = lane >> 2, tig = lane & 3;
    int q = blockIdx.x;

    // ---- stage: weights (coalesced copies of prepped images) + misc ----
    {
        const uint4* s2 = (const uint4*)g_w2h;
        uint4* d2 = (uint4*)w2s;
        for (int i = tid; i < 4224; i += 640) d2[i] = s2[i];
        const uint4* s3 = (const uint4*)g_w3h;
        uint4* d3 = (uint4*)w3s;
        for (int i = tid; i < 1088; i += 640) d3[i] = s3[i];
        for (int idx = tid; idx < 1024; idx += 640) {
            int k = idx >> 4, nn = idx & 15;
            W4s[idx] = (nn < 10) ? W4[k * 10 + nn] : 0.f;
        }
        if (tid < 64) ((float4*)qp)[tid] = ((const float4*)(g_qproj + q * H0))[tid];
        if (tid >= 64 && tid < 192) b2s[tid - 64] = b2[tid - 64];
        if (tid >= 192 && tid < 256) b3s[tid - 192] = b3[tid - 192];
        if (tid >= 256 && tid < 272) b4s[tid - 256] = (tid - 256 < 10) ? b4[tid - 256] : 0.f;
        if (tid >= 272 && tid < 288) cls[tid - 272] = 0.f;
    }
    __syncthreads();

    // ---- build h1 = fp16(relu(qproj[q] + iproj[item])), [m][k2] words ----
    {
        const float4* ip4 = (const float4*)g_iproj;
        const float4* qp4 = (const float4*)qp;
        for (int idx = tid; idx < 160 * 64; idx += 640) {
            int m = idx >> 6, k4 = idx & 63;
            float4 a = ip4[m * 64 + k4];
            float4 b = qp4[k4];
            __half2 lo = __floats2half2_rn(fmaxf(a.x + b.x, 0.f), fmaxf(a.y + b.y, 0.f));
            __half2 hi = __floats2half2_rn(fmaxf(a.z + b.z, 0.f), fmaxf(a.w + b.w, 0.f));
            h1w[m * 132 + 2 * k4] = h2u(lo);
            h1w[m * 132 + 2 * k4 + 1] = h2u(hi);
        }
    }
    __syncthreads();

    // ---------------- layer 2: [160,256] @ [256,128], fp16 + ldmatrix ----
    int mb = (warp >> 2) * 32, nb = (warp & 3) * 32;
    float d[2][4][4];
#pragma unroll
    for (int a = 0; a < 2; a++)
#pragma unroll
        for (int b = 0; b < 4; b++)
#pragma unroll
            for (int c = 0; c < 4; c++) d[a][b][c] = 0.f;

    {
        int t = lane >> 3, rr = lane & 7;
        // A tiles: t&1 -> m-half (+8), t>>1 -> k-half (+4 words)
        unsigned aA0 = sm_u32(h1w + (mb + (t & 1) * 8 + rr) * 132 + (t >> 1) * 4);
        unsigned aA1 = aA0 + 16 * 132 * 4;
        // B tiles: t>>1 -> n-half (+8), t&1 -> k-half (+4 words)
        unsigned bA0 = sm_u32(w2s + (nb + (t >> 1) * 8 + rr) * 132 + (t & 1) * 4);
        unsigned bA1 = bA0 + 16 * 132 * 4;
#pragma unroll
        for (int c = 0; c < 16; c++) {
            unsigned a0[4], a1[4], u0[4], u1[4];
            ldsm4(a0, aA0 + c * 32);
            ldsm4(a1, aA1 + c * 32);
            ldsm4(u0, bA0 + c * 32);
            ldsm4(u1, bA1 + c * 32);
            mma16(d[0][0], a0, u0);
            mma16(d[0][1], a0, u0 + 2);
            mma16(d[0][2], a0, u1);
            mma16(d[0][3], a0, u1 + 2);
            mma16(d[1][0], a1, u0);
            mma16(d[1][1], a1, u0 + 2);
            mma16(d[1][2], a1, u1);
            mma16(d[1][3], a1, u1 + 2);
        }
    }
    __syncthreads();

    // layer-2 epilogue -> h2 (half2 words, aliases h1)
#pragma unroll
    for (int mi = 0; mi < 2; mi++) {
#pragma unroll
        for (int ni = 0; ni < 4; ni++) {
            int n = nb + ni * 8 + tig * 2;
            int w = ((nb + ni * 8) >> 1) + tig;
            int mlo = mb + mi * 16 + gid, mhi = mlo + 8;
            __half2 vlo = __floats2half2_rn(fmaxf(d[mi][ni][0] + b2s[n], 0.f),
                                            fmaxf(d[mi][ni][1] + b2s[n + 1], 0.f));
            __half2 vhi = __floats2half2_rn(fmaxf(d[mi][ni][2] + b2s[n], 0.f),
                                            fmaxf(d[mi][ni][3] + b2s[n + 1], 0.f));
            h2w[mlo * 68 + w] = h2u(vlo);
            h2w[mhi * 68 + w] = h2u(vhi);
        }
    }
    __syncthreads();

    // ---------------- layer 3: [160,128] @ [128,64], fp16 + ldmatrix ----
    int mb3 = (warp >> 1) * 16, nb3 = (warp & 1) * 32;
    float e[4][4];
#pragma unroll
    for (int b = 0; b < 4; b++)
#pragma unroll
        for (int c = 0; c < 4; c++) e[b][c] = 0.f;

    {
        int t = lane >> 3, rr = lane & 7;
        unsigned aA = sm_u32(h2w + (mb3 + (t & 1) * 8 + rr) * 68 + (t >> 1) * 4);
        unsigned bA0 = sm_u32(w3s + (nb3 + (t >> 1) * 8 + rr) * 68 + (t & 1) * 4);
        unsigned bA1 = bA0 + 16 * 68 * 4;
#pragma unroll
        for (int c = 0; c < 8; c++) {
            unsigned a[4], u0[4], u1[4];
            ldsm4(a, aA + c * 32);
            ldsm4(u0, bA0 + c * 32);
            ldsm4(u1, bA1 + c * 32);
            mma16(e[0], a, u0);
            mma16(e[1], a, u0 + 2);
            mma16(e[2], a, u1);
            mma16(e[3], a, u1 + 2);
        }
    }

    // layer-3 epilogue -> h3 (f32, dead w2s region)
#pragma unroll
    for (int ni = 0; ni < 4; ni++) {
        int n = nb3 + ni * 8 + tig * 2;
        int mlo = mb3 + gid, mhi = mlo + 8;
        h3f[mlo * 68 + n] = fmaxf(e[ni][0] + b3s[n], 0.f);
        h3f[mlo * 68 + n + 1] = fmaxf(e[ni][1] + b3s[n + 1], 0.f);
        h3f[mhi * 68 + n] = fmaxf(e[ni][2] + b3s[n], 0.f);
        h3f[mhi * 68 + n + 1] = fmaxf(e[ni][3] + b3s[n + 1], 0.f);
    }
    __syncthreads();

    // ---------------- layer 4 + tanh + mean/sum reduction ----------------
#pragma unroll
    for (int it = 0; it < 4; it++) {
        int idx = tid + it * 640;
        int r = idx >> 4, nn = idx & 15;
        float acc = b4s[nn];
#pragma unroll 8
        for (int k = 0; k < 64; k++)
            acc = fmaf(h3f[r * 68 + k], W4s[k * 16 + nn], acc);
        float v = tanhf(acc);
#pragma unroll
        for (int o = 8; o; o >>= 1) v += __shfl_xor_sync(0xffffffffu, v, o);
        if ((lane & 15) == 0) atomicAdd(&cls[r >> 4], 0.1f * v);
    }
    __syncthreads();
    if (tid < 10) out[q * 10 + tid] = cls[tid];
}

// ---------------------------------------------------------------------------
extern "C" void kernel_launch(void* const* d_in, const int* in_sizes, int n_in,
                              void* d_out, int out_size) {
    const float* queries  = (const float*)d_in[0];
    const float* supports = (const float*)d_in[1];
    const float* W1 = (const float*)d_in[2];
    const float* b1 = (const float*)d_in[3];
    const float* W2 = (const float*)d_in[4];
    const float* b2 = (const float*)d_in[5];
    const float* W3 = (const float*)d_in[6];
    const float* b3 = (const float*)d_in[7];
    const float* W4 = (const float*)d_in[8];
    const float* b4 = (const float*)d_in[9];
    float* out = (float*)d_out;

    float* qproj;
    float* iproj;
    cudaGetSymbolAddress((void**)&qproj, g_qproj);
    cudaGetSymbolAddress((void**)&iproj, g_iproj);

    cudaFuncSetAttribute(proj_mma, cudaFuncAttributeMaxDynamicSharedMemorySize, PROJ_SMEM);
    cudaFuncSetAttribute(main_mma, cudaFuncAttributeMaxDynamicSharedMemorySize, MAIN_SMEM);

    // qproj/iproj (tf32, retiled M=64) and fp16 weight images
    proj_mma<<<dim3(35, 2), 256, PROJ_SMEM>>>(
        (const float4*)queries, (const float4*)supports, W1, b1, qproj, iproj);
    prep_w<<<80, 256>>>(W2, W3);
    // fused MLP + reduction (ldmatrix fragment loads)
    main_mma<<<QN, 640, MAIN_SMEM>>>(b2, b3, W4, b4, out);
}